// round 2
// baseline (speedup 1.0000x reference)
#include <cuda_runtime.h>
#include <math.h>
#include <stdint.h>

#define NN 100000
#define EE 1600000
#define FF 128
#define CC 10
#define KK 3
#define LL 8

#define FLAG_BETA 1
#define FLAG_BIAS 2
#define FLAG_ELU  4

// ---------------- static scratch (no allocation allowed) ----------------
__device__ float g_buf0[NN * FF];
__device__ float g_buf1[NN * FF];
__device__ float g_buf2[NN * FF];
__device__ float g_buf3[NN * FF];
__device__ float g_deg[NN];
__device__ float g_dis[NN];
__device__ int   g_cnt[NN];
__device__ int   g_cur[NN];
__device__ int   g_rowptr[NN + 1];
__device__ int   g_csrsrc[EE];
__device__ float g_csrw[EE];

// ---------------- setup kernels ----------------
__global__ void k_zero(int n) {
    int i = blockIdx.x * blockDim.x + threadIdx.x;
    if (i < n) { g_deg[i] = 0.f; g_cnt[i] = 0; g_cur[i] = 0; }
}

__global__ void k_count(const int* __restrict__ dst, const float* __restrict__ attr, int e) {
    int i = blockIdx.x * blockDim.x + threadIdx.x;
    if (i < e) {
        int d = __ldg(dst + i);
        atomicAdd(&g_deg[d], __ldg(attr + i));
        atomicAdd(&g_cnt[d], 1);
    }
}

__global__ void k_dis(int n) {
    int i = blockIdx.x * blockDim.x + threadIdx.x;
    if (i < n) {
        float d = g_deg[i];
        g_dis[i] = (d > 0.f) ? rsqrtf(d) : 0.f;
    }
}

// single-block exclusive scan of g_cnt -> g_rowptr (n = NN)
__global__ void k_scan(int n) {
    __shared__ int sh[1024];
    __shared__ int carry;
    int tid = threadIdx.x;
    if (tid == 0) carry = 0;
    __syncthreads();
    for (int base = 0; base < n; base += 1024) {
        int i = base + tid;
        int v = (i < n) ? g_cnt[i] : 0;
        sh[tid] = v;
        __syncthreads();
        for (int off = 1; off < 1024; off <<= 1) {
            int t = (tid >= off) ? sh[tid - off] : 0;
            __syncthreads();
            sh[tid] += t;
            __syncthreads();
        }
        int incl = sh[tid];
        int c = carry;
        if (i < n) g_rowptr[i] = c + incl - v;   // exclusive
        __syncthreads();
        if (tid == 1023) carry = c + sh[1023];
        __syncthreads();
    }
    if (tid == 0) g_rowptr[n] = carry;
}

__global__ void k_scatter(const int* __restrict__ src, const int* __restrict__ dst,
                          const float* __restrict__ attr, int e) {
    int i = blockIdx.x * blockDim.x + threadIdx.x;
    if (i < e) {
        int s = __ldg(src + i), d = __ldg(dst + i);
        float nv = g_dis[s] * __ldg(attr + i) * g_dis[d];
        int pos = g_rowptr[d] + atomicAdd(&g_cur[d], 1);
        g_csrsrc[pos] = s;
        g_csrw[pos]   = nv;
    }
}

// ---------------- SpMM: Hout[n,:] = sum_{e in row n} w_e * Hin[src_e,:] ----------------
// one warp per destination node, each lane owns 4 contiguous features (float4)
__global__ void k_spmm(const float* __restrict__ Hin, float* __restrict__ Hout, int n) {
    int wid  = (blockIdx.x * blockDim.x + threadIdx.x) >> 5;
    int lane = threadIdx.x & 31;
    if (wid >= n) return;
    int beg = g_rowptr[wid];
    int end = g_rowptr[wid + 1];
    float4 acc = make_float4(0.f, 0.f, 0.f, 0.f);
    int j = beg;
    // 2-edge unroll: two independent gathers in flight
    for (; j + 1 < end; j += 2) {
        int   s0 = g_csrsrc[j],     s1 = g_csrsrc[j + 1];
        float w0 = g_csrw[j],       w1 = g_csrw[j + 1];
        float4 v0 = __ldg((const float4*)(Hin + (size_t)s0 * FF + lane * 4));
        float4 v1 = __ldg((const float4*)(Hin + (size_t)s1 * FF + lane * 4));
        acc.x += w0 * v0.x + w1 * v1.x;
        acc.y += w0 * v0.y + w1 * v1.y;
        acc.z += w0 * v0.z + w1 * v1.z;
        acc.w += w0 * v0.w + w1 * v1.w;
    }
    if (j < end) {
        int   s = g_csrsrc[j];
        float w = g_csrw[j];
        float4 v = __ldg((const float4*)(Hin + (size_t)s * FF + lane * 4));
        acc.x += w * v.x;
        acc.y += w * v.y;
        acc.z += w * v.z;
        acc.w += w * v.w;
    }
    *(float4*)(Hout + (size_t)wid * FF + lane * 4) = acc;
}

// ---------------- GEMM: O[n, 0:128] (+)= A[n, 0:128] @ W[128,128] (+bias)(+elu) ----------------
// 128-row tile per block, BK=32, 256 threads, 8x8 microtile per thread (strided 16)
__global__ __launch_bounds__(256) void k_gemmF(
    const float* __restrict__ A, const float* __restrict__ W,
    const float* __restrict__ bias, float* __restrict__ O,
    int nRows, int flags)
{
    __shared__ float As[128][36];   // [row][k], padded stride 36 (float4-storable)
    __shared__ float Ws[32][128];   // [k][col]

    int tid = threadIdx.x;
    int tx = tid & 15;        // col group 0..15
    int ty = tid >> 4;        // row group 0..15
    int row0 = blockIdx.x * 128;

    float acc[8][8];
#pragma unroll
    for (int i = 0; i < 8; i++)
#pragma unroll
        for (int j = 0; j < 8; j++) acc[i][j] = 0.f;

    for (int kt = 0; kt < FF; kt += 32) {
        // load A tile 128x32 (coalesced float4)
#pragma unroll
        for (int p = 0; p < 4; p++) {
            int t  = tid + p * 256;
            int r  = t >> 3;          // 0..127
            int c4 = (t & 7) << 2;    // 0..28
            int gr = row0 + r;
            float4 v = make_float4(0.f, 0.f, 0.f, 0.f);
            if (gr < nRows) v = *(const float4*)(A + (size_t)gr * FF + kt + c4);
            *(float4*)(&As[r][c4]) = v;
        }
        // load W tile 32x128
#pragma unroll
        for (int p = 0; p < 4; p++) {
            int t  = tid + p * 256;
            int k  = t >> 5;          // 0..31
            int c4 = (t & 31) << 2;   // 0..124
            *(float4*)(&Ws[k][c4]) = *(const float4*)(W + (size_t)(kt + k) * FF + c4);
        }
        __syncthreads();

#pragma unroll
        for (int k = 0; k < 32; k++) {
            float a[8], b[8];
#pragma unroll
            for (int i = 0; i < 8; i++) a[i] = As[ty + 16 * i][k];
#pragma unroll
            for (int j = 0; j < 8; j++) b[j] = Ws[k][tx + 16 * j];
#pragma unroll
            for (int i = 0; i < 8; i++)
#pragma unroll
                for (int j = 0; j < 8; j++)
                    acc[i][j] += a[i] * b[j];
        }
        __syncthreads();
    }

    float bv[8];
#pragma unroll
    for (int j = 0; j < 8; j++)
        bv[j] = (flags & FLAG_BIAS) ? bias[tx + 16 * j] : 0.f;

#pragma unroll
    for (int i = 0; i < 8; i++) {
        int gr = row0 + ty + 16 * i;
        if (gr < nRows) {
#pragma unroll
            for (int j = 0; j < 8; j++) {
                int gc = tx + 16 * j;
                float c = acc[i][j] + bv[j];
                if (flags & FLAG_BETA) c += O[(size_t)gr * FF + gc];
                if (flags & FLAG_ELU)  c = (c > 0.f) ? c : expm1f(c);
                O[(size_t)gr * FF + gc] = c;
            }
        }
    }
}

// ---------------- Output GEMM: O[n, 0:10] (+)= A[n,0:128] @ W[128,10] (+bias) ----------------
__global__ __launch_bounds__(256) void k_gemmC(
    const float* __restrict__ A, const float* __restrict__ W,
    const float* __restrict__ bias, float* __restrict__ O,
    int nRows, int flags)
{
    __shared__ float Ws[FF * CC];
    __shared__ float bs[CC];
    int tid = threadIdx.x;
    for (int i = tid; i < FF * CC; i += 256) Ws[i] = W[i];
    if (tid < CC) bs[tid] = (flags & FLAG_BIAS) ? bias[tid] : 0.f;
    __syncthreads();

    int row = blockIdx.x * 256 + tid;
    if (row >= nRows) return;

    float acc[CC];
#pragma unroll
    for (int c = 0; c < CC; c++) acc[c] = 0.f;

    const float* a = A + (size_t)row * FF;
#pragma unroll 4
    for (int k = 0; k < FF; k++) {
        float av = a[k];
#pragma unroll
        for (int c = 0; c < CC; c++) acc[c] += av * Ws[k * CC + c];
    }
#pragma unroll
    for (int c = 0; c < CC; c++) {
        float v = acc[c] + bs[c];
        if (flags & FLAG_BETA) v += O[(size_t)row * CC + c];
        O[(size_t)row * CC + c] = v;
    }
}

// ---------------- host orchestration ----------------
static float* s_buf0 = nullptr;
static float* s_buf1 = nullptr;
static float* s_t1   = nullptr;
static float* s_t2   = nullptr;

extern "C" void kernel_launch(void* const* d_in, const int* in_sizes, int n_in,
                              void* d_out, int out_size) {
    const float* x    = (const float*)d_in[0];
    const int*   ei   = (const int*)d_in[1];      // [2, E]: src then dst
    const float* attr = (const float*)d_in[2];
    const float* Wh   = (const float*)d_in[3];    // [8, 4, 128, 128]
    const float* bh   = (const float*)d_in[4];    // [8, 128]
    const float* Wo   = (const float*)d_in[5];    // [4, 128, 10]
    const float* bo   = (const float*)d_in[6];    // [10]
    float* out = (float*)d_out;

    const int N = NN, E = EE;
    const int* srcp = ei;
    const int* dstp = ei + E;

    if (!s_buf0) {   // resolved once, outside any capture-sensitive path on replays
        void* p;
        cudaGetSymbolAddress(&p, g_buf0); s_buf0 = (float*)p;
        cudaGetSymbolAddress(&p, g_buf1); s_buf1 = (float*)p;
        cudaGetSymbolAddress(&p, g_buf2); s_t1   = (float*)p;
        cudaGetSymbolAddress(&p, g_buf3); s_t2   = (float*)p;
    }
    float* buf0 = s_buf0;
    float* buf1 = s_buf1;
    float* t1   = s_t1;
    float* t2   = s_t2;

    dim3 b256(256);
    int gN = (N + 255) / 256;
    int gE = (E + 255) / 256;

    // normalization + CSR build
    k_zero<<<gN, b256>>>(N);
    k_count<<<gE, b256>>>(dstp, attr, E);
    k_dis<<<gN, b256>>>(N);
    k_scan<<<1, 1024>>>(N);
    k_scatter<<<gE, b256>>>(srcp, dstp, attr, E);

    int gGemm = (N + 127) / 128;
    int gSpmm = (N * 32 + 255) / 256;

    const float* X = x;
    for (int l = 0; l < LL; l++) {
        float* acc = (l & 1) ? buf1 : buf0;
        const float* Wl = Wh + (size_t)l * (KK + 1) * FF * FF;
        const float* bl = bh + (size_t)l * FF;

        k_gemmF<<<gGemm, b256>>>(X, Wl, bl, acc, N, FLAG_BIAS);

        const float* p = X;
        for (int k = 1; k <= KK; k++) {
            float* o = (k & 1) ? t1 : t2;
            k_spmm<<<gSpmm, b256>>>(p, o, N);
            int fl = FLAG_BETA | ((k == KK) ? FLAG_ELU : 0);
            k_gemmF<<<gGemm, b256>>>(o, Wl + (size_t)k * FF * FF, nullptr, acc, N, fl);
            p = o;
        }
        X = acc;
    }

    // output layer (no ELU)
    int gC = (N + 255) / 256;
    k_gemmC<<<gC, b256>>>(X, Wo, bo, out, N, FLAG_BIAS);
    const float* p = X;
    for (int k = 1; k <= KK; k++) {
        float* o = (k & 1) ? t1 : t2;
        k_spmm<<<gSpmm, b256>>>(p, o, N);
        k_gemmC<<<gC, b256>>>(o, Wo + (size_t)k * FF * CC, nullptr, out, N, FLAG_BETA);
        p = o;
    }
}

// round 4
// speedup vs baseline: 2.4780x; 2.4780x over previous
#include <cuda_runtime.h>
#include <cuda_bf16.h>
#include <math.h>
#include <stdint.h>

#define NN 100000
#define EE 1600000
#define FF 128
#define CC 10
#define KK 3
#define LL 8
#define NB ((NN + 255) / 256)

// ---------------- static scratch ----------------
__device__ float g_bufA[NN * FF];
__device__ float g_bufB[NN * FF];
__device__ float g_h1[NN * FF];
__device__ float g_h2[NN * FF];
__device__ float g_h3[NN * FF];
__device__ float g_deg[NN];
__device__ float g_dis[NN];
__device__ int   g_cnt[NN];
__device__ int   g_cur[NN];
__device__ int   g_rowptr[NN + 1];
__device__ int   g_csrsrc[EE];
__device__ float g_csrw[EE];
__device__ int   g_bsum[512];
__device__ int   g_boff[512];
__device__ __nv_bfloat16 g_Whi[LL * FF * 512];   // [l][n_out 128][k 512] K-major
__device__ __nv_bfloat16 g_Wlo[LL * FF * 512];

// ---------------- helpers ----------------
__device__ __forceinline__ uint32_t smem_u32(const void* p) {
    uint32_t a;
    asm("{ .reg .u64 t; cvta.to.shared.u64 t, %1; cvt.u32.u64 %0, t; }" : "=r"(a) : "l"(p));
    return a;
}
#define SW128(o) ((o) ^ ((((o) >> 3) & 0x70)))

#define STS128V(addr, a, b, c, d) \
    asm volatile("st.shared.v4.b32 [%0], {%1, %2, %3, %4};" \
                 :: "r"((uint32_t)(addr)), "r"(a), "r"(b), "r"(c), "r"(d) : "memory")

__device__ __forceinline__ void ldmat_x4(uint32_t* r, uint32_t addr) {
    asm volatile("ldmatrix.sync.aligned.m8n8.x4.shared.b16 {%0,%1,%2,%3}, [%4];"
                 : "=r"(r[0]), "=r"(r[1]), "=r"(r[2]), "=r"(r[3]) : "r"(addr));
}

__device__ __forceinline__ void mma_bf16(float* d, const uint32_t* a, const uint32_t* b) {
    asm volatile(
        "mma.sync.aligned.m16n8k16.row.col.f32.bf16.bf16.f32 "
        "{%0,%1,%2,%3}, {%4,%5,%6,%7}, {%8,%9}, {%0,%1,%2,%3};"
        : "+f"(d[0]), "+f"(d[1]), "+f"(d[2]), "+f"(d[3])
        : "r"(a[0]), "r"(a[1]), "r"(a[2]), "r"(a[3]), "r"(b[0]), "r"(b[1]));
}

// ---------------- setup kernels ----------------
__global__ void k_zero(int n) {
    int i = blockIdx.x * blockDim.x + threadIdx.x;
    if (i < n) { g_deg[i] = 0.f; g_cnt[i] = 0; g_cur[i] = 0; }
}

__global__ void k_count(const int* __restrict__ dst, const float* __restrict__ attr, int e) {
    int i = blockIdx.x * blockDim.x + threadIdx.x;
    if (i < e) {
        int d = __ldg(dst + i);
        atomicAdd(&g_deg[d], __ldg(attr + i));
        atomicAdd(&g_cnt[d], 1);
    }
}

__global__ void k_dis(int n) {
    int i = blockIdx.x * blockDim.x + threadIdx.x;
    if (i < n) {
        float d = g_deg[i];
        g_dis[i] = (d > 0.f) ? rsqrtf(d) : 0.f;
    }
}

__global__ void k_scanA(int n) {
    __shared__ int sh[256];
    int b = blockIdx.x, t = threadIdx.x, i = b * 256 + t;
    int v = (i < n) ? g_cnt[i] : 0;
    sh[t] = v;
    __syncthreads();
    for (int off = 1; off < 256; off <<= 1) {
        int u = (t >= off) ? sh[t - off] : 0;
        __syncthreads();
        sh[t] += u;
        __syncthreads();
    }
    if (i < n) g_rowptr[i] = sh[t] - v;
    if (t == 255) g_bsum[b] = sh[255];
}

__global__ void k_scanB(int nb) {
    __shared__ int sh[512];
    int t = threadIdx.x;
    int v = (t < nb) ? g_bsum[t] : 0;
    sh[t] = v;
    __syncthreads();
    for (int off = 1; off < 512; off <<= 1) {
        int u = (t >= off) ? sh[t - off] : 0;
        __syncthreads();
        sh[t] += u;
        __syncthreads();
    }
    g_boff[t] = sh[t] - v;
}

__global__ void k_scanC(int n) {
    int b = blockIdx.x, i = b * 256 + threadIdx.x;
    if (i < n) g_rowptr[i] += g_boff[b];
    if (i == 0) g_rowptr[n] = EE;
}

__global__ void k_scatter(const int* __restrict__ src, const int* __restrict__ dst,
                          const float* __restrict__ attr, int e) {
    int i = blockIdx.x * blockDim.x + threadIdx.x;
    if (i < e) {
        int s = __ldg(src + i), d = __ldg(dst + i);
        float nv = g_dis[s] * __ldg(attr + i) * g_dis[d];
        int pos = g_rowptr[d] + atomicAdd(&g_cur[d], 1);
        g_csrsrc[pos] = s;
        g_csrw[pos]   = nv;
    }
}

// convert hidden weights [8][4][128][128] (l,k,kin,n) -> hi/lo bf16 [l][n][k*128+kin]
__global__ void k_cvtW(const float* __restrict__ Wh) {
    int idx = blockIdx.x * blockDim.x + threadIdx.x;
    if (idx >= LL * 4 * FF * FF) return;
    int n   = idx & 127;
    int kin = (idx >> 7) & 127;
    int k   = (idx >> 14) & 3;
    int l   = idx >> 16;
    float w = Wh[idx];
    __nv_bfloat16 hi = __float2bfloat16(w);
    __nv_bfloat16 lo = __float2bfloat16(w - __bfloat162float(hi));
    size_t dst = ((size_t)l * FF + n) * 512 + k * FF + kin;
    g_Whi[dst] = hi;
    g_Wlo[dst] = lo;
}

// ---------------- SpMM width-128 (fp32) ----------------
__global__ void k_spmm(const float* __restrict__ Hin, float* __restrict__ Hout, int n) {
    int wid  = (blockIdx.x * blockDim.x + threadIdx.x) >> 5;
    int lane = threadIdx.x & 31;
    if (wid >= n) return;
    int beg = g_rowptr[wid];
    int end = g_rowptr[wid + 1];
    float4 acc = make_float4(0.f, 0.f, 0.f, 0.f);
    int j = beg;
    for (; j + 1 < end; j += 2) {
        int   s0 = g_csrsrc[j],     s1 = g_csrsrc[j + 1];
        float w0 = g_csrw[j],       w1 = g_csrw[j + 1];
        float4 v0 = __ldg((const float4*)(Hin + (size_t)s0 * FF + lane * 4));
        float4 v1 = __ldg((const float4*)(Hin + (size_t)s1 * FF + lane * 4));
        acc.x += w0 * v0.x + w1 * v1.x;
        acc.y += w0 * v0.y + w1 * v1.y;
        acc.z += w0 * v0.z + w1 * v1.z;
        acc.w += w0 * v0.w + w1 * v1.w;
    }
    if (j < end) {
        int   s = g_csrsrc[j];
        float w = g_csrw[j];
        float4 v = __ldg((const float4*)(Hin + (size_t)s * FF + lane * 4));
        acc.x += w * v.x;
        acc.y += w * v.y;
        acc.z += w * v.z;
        acc.w += w * v.w;
    }
    *(float4*)(Hout + (size_t)wid * FF + lane * 4) = acc;
}

// ---------------- fused TAGConv layer GEMM (mma.sync bf16 split) ----------------
// O[128 rows, 128] = ELU( [X|H1|H2|H3] (K=512) @ W + bias )
// smem regions (dynamic, 64KB): Ah +0, Al +16K, Bh +32K, Bl +48K
// each region: 128 rows x 64 bf16, 128B/row, SW128 swizzle within region
__global__ __launch_bounds__(256, 1) void k_tagF(
    const float* __restrict__ X, const float* __restrict__ H1,
    const float* __restrict__ H2, const float* __restrict__ H3,
    const __nv_bfloat16* __restrict__ WBh, const __nv_bfloat16* __restrict__ WBl,
    const float* __restrict__ bias, float* __restrict__ O, int nRows)
{
    extern __shared__ char smem[];
    uint32_t sA = smem_u32(smem);
    uint32_t sAl = sA + 16384;
    uint32_t sB  = sA + 32768;
    uint32_t sBl = sA + 49152;

    int tid  = threadIdx.x;
    int wid  = tid >> 5;
    int lane = tid & 31;
    int row0 = blockIdx.x * 128;

    int m0 = (wid >> 1) * 32;     // warp m-offset (0,32,64,96)
    int n0 = (wid & 1) * 64;      // warp n-offset (0,64)

    float acc[2][8][4];
#pragma unroll
    for (int mt = 0; mt < 2; mt++)
#pragma unroll
        for (int nt = 0; nt < 8; nt++)
#pragma unroll
            for (int q = 0; q < 4; q++) acc[mt][nt][q] = 0.f;

    const float* srcs[4] = {X, H1, H2, H3};

    for (int t = 0; t < 8; t++) {
        // ---- stage A: 128 rows x 64 k fp32 -> hi/lo bf16, SW128 ----
        const float* Asrc = srcs[t >> 1];
        int col0 = (t & 1) * 64;
#pragma unroll
        for (int g = tid; g < 1024; g += 256) {
            int r  = g >> 3;
            int k8 = (g & 7) << 3;
            float4 v0, v1;
            if (row0 + r < nRows) {
                const float* p = Asrc + (size_t)(row0 + r) * FF + col0 + k8;
                v0 = *(const float4*)p;
                v1 = *(const float4*)(p + 4);
            } else {
                v0 = make_float4(0.f, 0.f, 0.f, 0.f);
                v1 = v0;
            }
            float f[8] = {v0.x, v0.y, v0.z, v0.w, v1.x, v1.y, v1.z, v1.w};
            uint32_t hi[4], lo[4];
#pragma unroll
            for (int i = 0; i < 4; i++) {
                __nv_bfloat16 h0 = __float2bfloat16(f[2 * i]);
                __nv_bfloat16 h1 = __float2bfloat16(f[2 * i + 1]);
                __nv_bfloat16 l0 = __float2bfloat16(f[2 * i] - __bfloat162float(h0));
                __nv_bfloat16 l1 = __float2bfloat16(f[2 * i + 1] - __bfloat162float(h1));
                hi[i] = (uint32_t)(*(uint16_t*)&h0) | ((uint32_t)(*(uint16_t*)&h1) << 16);
                lo[i] = (uint32_t)(*(uint16_t*)&l0) | ((uint32_t)(*(uint16_t*)&l1) << 16);
            }
            uint32_t off = SW128((uint32_t)(r * 128 + k8 * 2));
            STS128V(sA  + off, hi[0], hi[1], hi[2], hi[3]);
            STS128V(sAl + off, lo[0], lo[1], lo[2], lo[3]);
        }
        // ---- stage B: 128 n-rows x 64 k from preconverted bf16 ----
        int kt64 = t * 64;
#pragma unroll
        for (int c = tid; c < 1024; c += 256) {
            int n  = c >> 3;
            int k8 = (c & 7) << 3;
            uint4 vh = *(const uint4*)(WBh + (size_t)n * 512 + kt64 + k8);
            uint4 vl = *(const uint4*)(WBl + (size_t)n * 512 + kt64 + k8);
            uint32_t off = SW128((uint32_t)(n * 128 + k8 * 2));
            STS128V(sB  + off, vh.x, vh.y, vh.z, vh.w);
            STS128V(sBl + off, vl.x, vl.y, vl.z, vl.w);
        }
        __syncthreads();

        // ---- compute: 4 k16-steps ----
        // A frag addr: row = m0 + mt*16 + lane%16, kbyte = ks*32 + (lane/16)*16
        // B frag addr (x4, two n-tiles): q=lane/8: n = nt0*8 + (q>>1)*8 + lane%8, kbyte = ks*32 + (q&1)*16
        int ar  = lane & 15;
        int ac  = (lane >> 4) << 4;       // 0 or 16 bytes
        int bq  = lane >> 3;
        int bn  = ((bq >> 1) << 3) + (lane & 7);
        int bc  = (bq & 1) << 4;          // 0 or 16 bytes
#pragma unroll
        for (int ks = 0; ks < 4; ks++) {
            int kb = ks * 32;
            uint32_t ah[2][4], al_[2][4];
#pragma unroll
            for (int mt = 0; mt < 2; mt++) {
                uint32_t off = SW128((uint32_t)((m0 + mt * 16 + ar) * 128 + kb + ac));
                ldmat_x4(ah[mt],  sA  + off);
                ldmat_x4(al_[mt], sAl + off);
            }
            uint32_t bh[8][2], bl_[8][2];
#pragma unroll
            for (int np = 0; np < 4; np++) {     // pairs of n-tiles
                uint32_t off = SW128((uint32_t)((n0 + np * 16 + bn) * 128 + kb + bc));
                uint32_t r4[4], l4[4];
                ldmat_x4(r4, sB  + off);
                ldmat_x4(l4, sBl + off);
                bh[np * 2][0] = r4[0];  bh[np * 2][1] = r4[1];
                bh[np * 2 + 1][0] = r4[2]; bh[np * 2 + 1][1] = r4[3];
                bl_[np * 2][0] = l4[0]; bl_[np * 2][1] = l4[1];
                bl_[np * 2 + 1][0] = l4[2]; bl_[np * 2 + 1][1] = l4[3];
            }
#pragma unroll
            for (int mt = 0; mt < 2; mt++)
#pragma unroll
                for (int nt = 0; nt < 8; nt++) {
                    mma_bf16(acc[mt][nt], ah[mt],  bh[nt]);
                    mma_bf16(acc[mt][nt], ah[mt],  bl_[nt]);
                    mma_bf16(acc[mt][nt], al_[mt], bh[nt]);
                }
        }
        __syncthreads();
    }

    // ---- epilogue: bias + ELU + store ----
    int erow = lane >> 2;         // 0..7
    int ecol = (lane & 3) * 2;    // 0,2,4,6
#pragma unroll
    for (int mt = 0; mt < 2; mt++) {
#pragma unroll
        for (int half = 0; half < 2; half++) {
            int r = row0 + m0 + mt * 16 + half * 8 + erow;
            if (r < nRows) {
#pragma unroll
                for (int nt = 0; nt < 8; nt++) {
                    int c = n0 + nt * 8 + ecol;
                    float v0 = acc[mt][nt][half * 2]     + bias[c];
                    float v1 = acc[mt][nt][half * 2 + 1] + bias[c + 1];
                    v0 = (v0 > 0.f) ? v0 : expm1f(v0);
                    v1 = (v1 > 0.f) ? v1 : expm1f(v1);
                    *(float2*)(O + (size_t)r * FF + c) = make_float2(v0, v1);
                }
            }
        }
    }
}

// ---------------- output layer: z_k = X @ Wo_k, all k in one pass ----------------
__global__ __launch_bounds__(256) void k_outGemm(
    const float* __restrict__ X, const float* __restrict__ Wo,
    float* __restrict__ Z, int nRows)
{
    __shared__ float Ws[4 * FF * CC];
    int tid = threadIdx.x;
    for (int i = tid; i < 4 * FF * CC; i += 256) Ws[i] = Wo[i];
    __syncthreads();

    int row = blockIdx.x * 256 + tid;
    if (row >= nRows) return;

    float acc[4 * CC];
#pragma unroll
    for (int i = 0; i < 4 * CC; i++) acc[i] = 0.f;

    const float* a = X + (size_t)row * FF;
    for (int k0 = 0; k0 < FF; k0 += 4) {
        float4 xv = *(const float4*)(a + k0);
        float xs[4] = {xv.x, xv.y, xv.z, xv.w};
#pragma unroll
        for (int q = 0; q < 4; q++) {
            float x = xs[q];
#pragma unroll
            for (int k4 = 0; k4 < 4; k4++) {
                const float* w = &Ws[(k4 * FF + k0 + q) * CC];
#pragma unroll
                for (int c = 0; c < CC; c++) acc[k4 * CC + c] += x * w[c];
            }
        }
    }
#pragma unroll
    for (int k4 = 0; k4 < 4; k4++)
#pragma unroll
        for (int c = 0; c < CC; c++)
            Z[(size_t)k4 * NN * CC + (size_t)row * CC + c] = acc[k4 * CC + c];
}

// ---------------- width-10 SpMM + add (Horner step) ----------------
__global__ void k_spmmC(const float* __restrict__ Hin, const float* __restrict__ Zadd,
                        const float* __restrict__ bo, float* __restrict__ Hout, int n)
{
    int gt = blockIdx.x * blockDim.x + threadIdx.x;
    int node = gt >> 4;
    int c = gt & 15;
    if (node >= n || c >= CC) return;
    int beg = g_rowptr[node], end = g_rowptr[node + 1];
    float acc = 0.f;
    for (int j = beg; j < end; j++)
        acc += g_csrw[j] * __ldg(Hin + (size_t)g_csrsrc[j] * CC + c);
    float v = Zadd[(size_t)node * CC + c] + acc;
    if (bo) v += bo[c];
    Hout[(size_t)node * CC + c] = v;
}

// ---------------- host orchestration ----------------
static bool s_init = false;
static float* s_bufA; static float* s_bufB;
static float* s_h1;   static float* s_h2;   static float* s_h3;
static __nv_bfloat16* s_Whi; static __nv_bfloat16* s_Wlo;

extern "C" void kernel_launch(void* const* d_in, const int* in_sizes, int n_in,
                              void* d_out, int out_size) {
    const float* x    = (const float*)d_in[0];
    const int*   ei   = (const int*)d_in[1];
    const float* attr = (const float*)d_in[2];
    const float* Wh   = (const float*)d_in[3];
    const float* bh   = (const float*)d_in[4];
    const float* Wo   = (const float*)d_in[5];
    const float* bo   = (const float*)d_in[6];
    float* out = (float*)d_out;

    const int N = NN, E = EE;
    const int* srcp = ei;
    const int* dstp = ei + E;

    if (!s_init) {
        void* p;
        cudaGetSymbolAddress(&p, g_bufA); s_bufA = (float*)p;
        cudaGetSymbolAddress(&p, g_bufB); s_bufB = (float*)p;
        cudaGetSymbolAddress(&p, g_h1);   s_h1   = (float*)p;
        cudaGetSymbolAddress(&p, g_h2);   s_h2   = (float*)p;
        cudaGetSymbolAddress(&p, g_h3);   s_h3   = (float*)p;
        cudaGetSymbolAddress(&p, g_Whi);  s_Whi  = (__nv_bfloat16*)p;
        cudaGetSymbolAddress(&p, g_Wlo);  s_Wlo  = (__nv_bfloat16*)p;
        cudaFuncSetAttribute(k_tagF, cudaFuncAttributeMaxDynamicSharedMemorySize, 65536);
        s_init = true;
    }

    dim3 b256(256);
    int gN = (N + 255) / 256;
    int gE = (E + 255) / 256;

    // normalization + CSR build
    k_zero<<<gN, b256>>>(N);
    k_count<<<gE, b256>>>(dstp, attr, E);
    k_dis<<<gN, b256>>>(N);
    k_scanA<<<NB, b256>>>(N);
    k_scanB<<<1, 512>>>(NB);
    k_scanC<<<NB, b256>>>(N);
    k_scatter<<<gE, b256>>>(srcp, dstp, attr, E);
    k_cvtW<<<(LL * 4 * FF * FF + 255) / 256, b256>>>(Wh);

    int gGemm = (N + 127) / 128;
    int gSpmm = (N * 32 + 255) / 256;

    const float* X = x;
    for (int l = 0; l < LL; l++) {
        float* Xn = (l & 1) ? s_bufB : s_bufA;
        k_spmm<<<gSpmm, b256>>>(X, s_h1, N);
        k_spmm<<<gSpmm, b256>>>(s_h1, s_h2, N);
        k_spmm<<<gSpmm, b256>>>(s_h2, s_h3, N);
        k_tagF<<<gGemm, b256, 65536>>>(
            X, s_h1, s_h2, s_h3,
            s_Whi + (size_t)l * FF * 512, s_Wlo + (size_t)l * FF * 512,
            bh + (size_t)l * FF, Xn, N);
        X = Xn;
    }

    // output layer via Horner: out = z0 + b + A(z1 + A(z2 + A z3)), z_k = X @ Wo_k
    float* z  = s_h1;             // z_k at z + k*N*CC
    float* t1 = s_h2;
    float* t2 = s_h2 + (size_t)N * CC;
    k_outGemm<<<gN, b256>>>(X, Wo, z, N);
    int gSC = (N * 16 + 255) / 256;
    k_spmmC<<<gSC, b256>>>(z + 3 * (size_t)N * CC, z + 2 * (size_t)N * CC, nullptr, t1, N);
    k_spmmC<<<gSC, b256>>>(t1, z + 1 * (size_t)N * CC, nullptr, t2, N);
    k_spmmC<<<gSC, b256>>>(t2, z, bo, out, N);
}